// round 3
// baseline (speedup 1.0000x reference)
#include <cuda_runtime.h>

// Inputs (metadata order):
//   0: gt_rois  [1,N,5] f32  (x1,y1,x2,y2,cls)
//   1: rois     [1,N,5] f32  (b,x1,y1,x2,y2)
//   2: labels   [N]     i32
//   3: means[4] 4: stds[4] 5: inside_w[4]  (f32)
// Output: concat(targets[N,4], inside_w[N,4], outside_w[N,4]) f32
//
// 4 boxes / thread: 4 stride-5 records = 80B = 5 aligned float4 loads per array.

__global__ __launch_bounds__(256) void rcnn_target_v4(
    const float* __restrict__ gt,
    const float* __restrict__ rois,
    const int* __restrict__ labels,
    const float* __restrict__ means,
    const float* __restrict__ stds,
    const float* __restrict__ inw,
    float* __restrict__ out,
    int n)
{
    int t  = blockIdx.x * blockDim.x + threadIdx.x;
    long long i0 = 4ll * t;
    if (i0 >= n) return;

    float m0 = __ldg(means + 0), m1 = __ldg(means + 1), m2 = __ldg(means + 2), m3 = __ldg(means + 3);
    float rs0 = 1.0f / __ldg(stds + 0), rs1 = 1.0f / __ldg(stds + 1);
    float rs2 = 1.0f / __ldg(stds + 2), rs3 = 1.0f / __ldg(stds + 3);
    float w0 = __ldg(inw + 0), w1 = __ldg(inw + 1), w2 = __ldg(inw + 2), w3 = __ldg(inw + 3);

    long long nn4 = 4ll * n;

    if (i0 + 4 <= (long long)n) {
        // ---- vector fast path: 4 full records ----
        union { float4 v[5]; float f[20]; } G, R;
        const float4* g4 = reinterpret_cast<const float4*>(gt   + 5 * i0);
        const float4* r4 = reinterpret_cast<const float4*>(rois + 5 * i0);
        #pragma unroll
        for (int k = 0; k < 5; k++) G.v[k] = g4[k];
        #pragma unroll
        for (int k = 0; k < 5; k++) R.v[k] = r4[k];
        int4 lab = *reinterpret_cast<const int4*>(labels + i0);
        int labv[4] = {lab.x, lab.y, lab.z, lab.w};

        float4 T[4], IW[4], OW[4];
        #pragma unroll
        for (int k = 0; k < 4; k++) {
            float gx1 = G.f[5*k + 0], gy1 = G.f[5*k + 1];
            float gx2 = G.f[5*k + 2], gy2 = G.f[5*k + 3];
            float ex1 = R.f[5*k + 1], ey1 = R.f[5*k + 2];
            float ex2 = R.f[5*k + 3], ey2 = R.f[5*k + 4];

            float ew  = ex2 - ex1 + 1.0f;
            float eh  = ey2 - ey1 + 1.0f;
            float ecx = ex1 + 0.5f * ew;
            float ecy = ey1 + 0.5f * eh;
            float gw  = gx2 - gx1 + 1.0f;
            float gh  = gy2 - gy1 + 1.0f;
            float gcx = gx1 + 0.5f * gw;
            float gcy = gy1 + 0.5f * gh;

            float dx = __fdividef(gcx - ecx, ew);
            float dy = __fdividef(gcy - ecy, eh);
            float dw = __logf(__fdividef(gw, ew));
            float dh = __logf(__fdividef(gh, eh));

            bool pos = labv[k] > 0;
            T[k].x = pos ? (dx - m0) * rs0 : 0.0f;
            T[k].y = pos ? (dy - m1) * rs1 : 0.0f;
            T[k].z = pos ? (dw - m2) * rs2 : 0.0f;
            T[k].w = pos ? (dh - m3) * rs3 : 0.0f;

            IW[k].x = pos ? w0 : 0.0f;
            IW[k].y = pos ? w1 : 0.0f;
            IW[k].z = pos ? w2 : 0.0f;
            IW[k].w = pos ? w3 : 0.0f;

            OW[k].x = (IW[k].x > 0.0f) ? 1.0f : 0.0f;
            OW[k].y = (IW[k].y > 0.0f) ? 1.0f : 0.0f;
            OW[k].z = (IW[k].z > 0.0f) ? 1.0f : 0.0f;
            OW[k].w = (IW[k].w > 0.0f) ? 1.0f : 0.0f;
        }

        float4* ot = reinterpret_cast<float4*>(out + 4 * i0);
        float4* oi = reinterpret_cast<float4*>(out + nn4 + 4 * i0);
        float4* oo = reinterpret_cast<float4*>(out + 2 * nn4 + 4 * i0);
        #pragma unroll
        for (int k = 0; k < 4; k++) ot[k] = T[k];
        #pragma unroll
        for (int k = 0; k < 4; k++) oi[k] = IW[k];
        #pragma unroll
        for (int k = 0; k < 4; k++) oo[k] = OW[k];
    } else {
        // ---- scalar tail ----
        for (long long i = i0; i < (long long)n; i++) {
            const float* r = rois + 5 * i;
            const float* g = gt   + 5 * i;
            float ex1 = r[1], ey1 = r[2], ex2 = r[3], ey2 = r[4];
            float gx1 = g[0], gy1 = g[1], gx2 = g[2], gy2 = g[3];

            float ew  = ex2 - ex1 + 1.0f;
            float eh  = ey2 - ey1 + 1.0f;
            float ecx = ex1 + 0.5f * ew;
            float ecy = ey1 + 0.5f * eh;
            float gw  = gx2 - gx1 + 1.0f;
            float gh  = gy2 - gy1 + 1.0f;
            float gcx = gx1 + 0.5f * gw;
            float gcy = gy1 + 0.5f * gh;

            float dx = __fdividef(gcx - ecx, ew);
            float dy = __fdividef(gcy - ecy, eh);
            float dw = __logf(__fdividef(gw, ew));
            float dh = __logf(__fdividef(gh, eh));

            bool pos = labels[i] > 0;
            float4 T, IW, OW;
            T.x = pos ? (dx - m0) * rs0 : 0.0f;
            T.y = pos ? (dy - m1) * rs1 : 0.0f;
            T.z = pos ? (dw - m2) * rs2 : 0.0f;
            T.w = pos ? (dh - m3) * rs3 : 0.0f;
            IW.x = pos ? w0 : 0.0f;  IW.y = pos ? w1 : 0.0f;
            IW.z = pos ? w2 : 0.0f;  IW.w = pos ? w3 : 0.0f;
            OW.x = (IW.x > 0.0f) ? 1.0f : 0.0f;
            OW.y = (IW.y > 0.0f) ? 1.0f : 0.0f;
            OW.z = (IW.z > 0.0f) ? 1.0f : 0.0f;
            OW.w = (IW.w > 0.0f) ? 1.0f : 0.0f;

            reinterpret_cast<float4*>(out + 4 * i)[0]           = T;
            reinterpret_cast<float4*>(out + nn4 + 4 * i)[0]     = IW;
            reinterpret_cast<float4*>(out + 2 * nn4 + 4 * i)[0] = OW;
        }
    }
}

extern "C" void kernel_launch(void* const* d_in, const int* in_sizes, int n_in,
                              void* d_out, int out_size)
{
    const float* gt     = (const float*)d_in[0];
    const float* rois   = (const float*)d_in[1];
    const int*   labels = (const int*)d_in[2];
    const float* means  = (const float*)d_in[3];
    const float* stds   = (const float*)d_in[4];
    const float* inw    = (const float*)d_in[5];
    float*       out    = (float*)d_out;

    int n = in_sizes[2];
    int threads = 256;
    int boxes_per_block = threads * 4;
    int blocks = (n + boxes_per_block - 1) / boxes_per_block;
    rcnn_target_v4<<<blocks, threads>>>(gt, rois, labels, means, stds, inw, out, n);
}

// round 4
// speedup vs baseline: 1.1914x; 1.1914x over previous
#include <cuda_runtime.h>

// Inputs: 0 gt_rois[1,N,5] f32 | 1 rois[1,N,5] f32 | 2 labels[N] i32
//         3 means[4] | 4 stds[4] | 5 inside_w[4]
// Output: concat(targets[N,4], inside_w[N,4], outside_w[N,4]) f32
//
// Stride-5 AoS handled via smem staging: coalesced float4 block loads,
// then conflict-free (odd-stride) smem reads per record.

#define BOXES_PER_BLOCK 256

__global__ __launch_bounds__(256) void rcnn_target_smem(
    const float* __restrict__ gt,
    const float* __restrict__ rois,
    const int* __restrict__ labels,
    const float* __restrict__ means,
    const float* __restrict__ stds,
    const float* __restrict__ inw,
    float* __restrict__ out,
    int n)
{
    __shared__ float sg[BOXES_PER_BLOCK * 5];
    __shared__ float sr[BOXES_PER_BLOCK * 5];

    int tid  = threadIdx.x;
    long long base = (long long)blockIdx.x * BOXES_PER_BLOCK;
    int remaining = n - (int)base;
    if (remaining > BOXES_PER_BLOCK) remaining = BOXES_PER_BLOCK;

    // ---- coalesced staging: consecutive float4s across the block ----
    {
        long long f0 = 5 * base;               // float offset of chunk start (16B-aligned: 5120B*blk)
        int nfloats  = remaining * 5;
        int nf4      = nfloats >> 2;           // full float4s
        const float4* g4 = reinterpret_cast<const float4*>(gt   + f0);
        const float4* r4 = reinterpret_cast<const float4*>(rois + f0);
        float4* sg4 = reinterpret_cast<float4*>(sg);
        float4* sr4 = reinterpret_cast<float4*>(sr);
        for (int k = tid; k < nf4; k += BOXES_PER_BLOCK) {
            sg4[k] = g4[k];
            sr4[k] = r4[k];
        }
        // spill floats (only possible in the last block)
        for (int k = (nf4 << 2) + tid; k < nfloats; k += BOXES_PER_BLOCK) {
            sg[k] = gt[f0 + k];
            sr[k] = rois[f0 + k];
        }
    }

    // params (L2-resident broadcasts)
    float m0 = __ldg(means + 0), m1 = __ldg(means + 1), m2 = __ldg(means + 2), m3 = __ldg(means + 3);
    float rs0 = 1.0f / __ldg(stds + 0), rs1 = 1.0f / __ldg(stds + 1);
    float rs2 = 1.0f / __ldg(stds + 2), rs3 = 1.0f / __ldg(stds + 3);
    float w0 = __ldg(inw + 0), w1 = __ldg(inw + 1), w2 = __ldg(inw + 2), w3 = __ldg(inw + 3);

    __syncthreads();

    if (tid >= remaining) return;

    long long i = base + tid;
    bool pos = labels[i] > 0;

    // conflict-free smem reads (stride 5 words = odd -> bank permutation)
    const float* g = sg + 5 * tid;   // [x1,y1,x2,y2,cls]
    const float* r = sr + 5 * tid;   // [b,x1,y1,x2,y2]

    float gx1 = g[0], gy1 = g[1], gx2 = g[2], gy2 = g[3];
    float ex1 = r[1], ey1 = r[2], ex2 = r[3], ey2 = r[4];

    float ew  = ex2 - ex1 + 1.0f;
    float eh  = ey2 - ey1 + 1.0f;
    float ecx = ex1 + 0.5f * ew;
    float ecy = ey1 + 0.5f * eh;
    float gw  = gx2 - gx1 + 1.0f;
    float gh  = gy2 - gy1 + 1.0f;
    float gcx = gx1 + 0.5f * gw;
    float gcy = gy1 + 0.5f * gh;

    float dx = __fdividef(gcx - ecx, ew);
    float dy = __fdividef(gcy - ecy, eh);
    float dw = __logf(__fdividef(gw, ew));
    float dh = __logf(__fdividef(gh, eh));

    float4 T, IW, OW;
    T.x = pos ? (dx - m0) * rs0 : 0.0f;
    T.y = pos ? (dy - m1) * rs1 : 0.0f;
    T.z = pos ? (dw - m2) * rs2 : 0.0f;
    T.w = pos ? (dh - m3) * rs3 : 0.0f;

    IW.x = pos ? w0 : 0.0f;
    IW.y = pos ? w1 : 0.0f;
    IW.z = pos ? w2 : 0.0f;
    IW.w = pos ? w3 : 0.0f;

    OW.x = (IW.x > 0.0f) ? 1.0f : 0.0f;
    OW.y = (IW.y > 0.0f) ? 1.0f : 0.0f;
    OW.z = (IW.z > 0.0f) ? 1.0f : 0.0f;
    OW.w = (IW.w > 0.0f) ? 1.0f : 0.0f;

    long long nn4 = 4ll * n;
    reinterpret_cast<float4*>(out + 4 * i)[0]           = T;
    reinterpret_cast<float4*>(out + nn4 + 4 * i)[0]     = IW;
    reinterpret_cast<float4*>(out + 2 * nn4 + 4 * i)[0] = OW;
}

extern "C" void kernel_launch(void* const* d_in, const int* in_sizes, int n_in,
                              void* d_out, int out_size)
{
    const float* gt     = (const float*)d_in[0];
    const float* rois   = (const float*)d_in[1];
    const int*   labels = (const int*)d_in[2];
    const float* means  = (const float*)d_in[3];
    const float* stds   = (const float*)d_in[4];
    const float* inw    = (const float*)d_in[5];
    float*       out    = (float*)d_out;

    int n = in_sizes[2];
    int blocks = (n + BOXES_PER_BLOCK - 1) / BOXES_PER_BLOCK;
    rcnn_target_smem<<<blocks, BOXES_PER_BLOCK>>>(gt, rois, labels, means, stds, inw, out, n);
}